// round 11
// baseline (speedup 1.0000x reference)
#include <cuda_runtime.h>
#include <cuda_fp16.h>
#include <math.h>

// Problem constants
#define Nn   100000
#define Tt   64
#define Ee   1000000
#define ETOT (Ee + Nn)    // edges + self loops
#define NB   32           // nodes per LSTM block
#define HROW 80           // int8 h row stride in bytes (conflict-free)

// -------- scratch (device globals; no allocations allowed) ----------
__device__ float   g_h[Nn * 64];     // LSTM final hidden
__device__ __half2 g_xh2[Nn * 64];   // GAT features, word p = (head p/32, dims 2p%64)
__device__ __half2 g_acc2[Nn * 64];  // weighted message accumulator (fp16x2)
__device__ float   g_asrc[Nn * 2];
__device__ float   g_adst[Nn * 2];
__device__ float   g_z[Nn * 2];      // segment sum (fp32)
__device__ int     g_estride;        // 1 if edge_index is int32, 2 if int64
__device__ int     g_eoff;           // offset (in int32 words) of dst row
__device__ float   g_wscale;         // 127 / max|w_hh|
__device__ float   g_sdq;            // max|w_hh| / (127*127)

// ==================== probe: edge dtype + w_hh scale ===============
__global__ void detect_kernel(const int* __restrict__ ei32,
                              const float* __restrict__ w_hh)
{
    __shared__ float red[256];
    const int tid = threadIdx.x;
    float m = 0.f;
    for (int i = tid; i < 256 * 64; i += 256) m = fmaxf(m, fabsf(w_hh[i]));
    red[tid] = m;
    __syncthreads();
    for (int s = 128; s; s >>= 1) {
        if (tid < s) red[tid] = fmaxf(red[tid], red[tid + s]);
        __syncthreads();
    }
    if (tid == 0) {
        float wmax = fmaxf(red[0], 1e-20f);
        g_wscale = 127.f / wmax;
        g_sdq    = wmax / (127.f * 127.f);
        bool all0 = true;
        #pragma unroll
        for (int i = 1; i < 64; i += 2) all0 &= (ei32[i] == 0);
        g_estride = all0 ? 2 : 1;
        g_eoff    = all0 ? 2 * Ee : Ee;
    }
}

// ==================== helpers ======================================
__device__ __forceinline__ unsigned tanh2(unsigned x)
{
    unsigned y;
    asm("tanh.approx.f16x2 %0, %1;" : "=r"(y) : "r"(x));
    return y;
}
__device__ __forceinline__ __half2 u2h(unsigned u) { return *reinterpret_cast<__half2*>(&u); }
__device__ __forceinline__ unsigned h2u(__half2 h) { return *reinterpret_cast<unsigned*>(&h); }

__device__ __forceinline__ unsigned pack2(float lo, float hi)
{
    unsigned u;
    asm("cvt.rn.f16x2.f32 %0, %1, %2;" : "=r"(u) : "f"(hi), "f"(lo));
    return u;
}
// fp16x2 sigmoid: 0.5 + 0.5*tanh(0.5*x)
__device__ __forceinline__ __half2 sig2(unsigned u, __half2 half05)
{
    __half2 x = __hmul2(u2h(u), half05);
    return __hfma2(u2h(tanh2(h2u(x))), half05, half05);
}

// int8 mma: m16n8k32, s8 x s8 -> s32
__device__ __forceinline__ void mma_s8(int& d0, int& d1, int& d2, int& d3,
                                       unsigned a0, unsigned a1, unsigned a2, unsigned a3,
                                       unsigned b0, unsigned b1)
{
    asm("mma.sync.aligned.m16n8k32.row.col.s32.s8.s8.s32 "
        "{%0,%1,%2,%3}, {%4,%5,%6,%7}, {%8,%9}, {%0,%1,%2,%3};"
        : "+r"(d0), "+r"(d1), "+r"(d2), "+r"(d3)
        : "r"(a0), "r"(a1), "r"(a2), "r"(a3), "r"(b0), "r"(b1));
}

// ==================== LSTM (int8 tensor-core recurrence) ===========
// 256 threads = 8 warps, 32 nodes/block. Warp w owns gate dims
// j in [8w, 8w+8) for all four gates; W_hh int8-quantized into
// registers; h quantized to int8 in smem each step. m16n8k32 halves
// MMA instruction count vs fp16 (16/warp-step). Gate init (bias +
// x W_ih) and dequant run in exact fp32; activations fp16x2.
__global__ void __launch_bounds__(256, 2)
lstm_kernel(const float* __restrict__ x, const float* __restrict__ w_ih,
            const float* __restrict__ w_hh, const float* __restrict__ b_ih,
            const float* __restrict__ b_hh)
{
    __shared__ float2        xshf[Tt * NB];        // x [t][n] fp32 pairs
    __shared__ unsigned char hsh8[2][NB * HROW];   // double-buffered h int8

    const int tid  = threadIdx.x;
    const int base = blockIdx.x * NB;
    const int wid  = tid >> 5, lane = tid & 31;
    const int grp  = lane >> 2, tig = lane & 3;

    // x tile (coalesced): idx = n*64 + t
    for (int idx = tid; idx < NB * Tt; idx += 256) {
        int n = idx >> 6, t = idx & 63;
        xshf[t * NB + n] = *(const float2*)&x[(size_t)(base + n) * 128 + t * 2];
    }
    for (int i = tid; i < 2 * NB * HROW / 4; i += 256)
        ((unsigned*)hsh8)[i] = 0u;

    const int j0 = wid * 8 + 2 * tig;
    const float wscale = g_wscale;
    const float sdq    = g_sdq;

    // fp32 step-invariant constants for gate init
    float bias_[4][2], wa_[4][2], wb_[4][2];
    #pragma unroll
    for (int q = 0; q < 4; ++q) {
        #pragma unroll
        for (int jc = 0; jc < 2; ++jc) {
            int g = q * 64 + j0 + jc;
            bias_[q][jc] = b_ih[g] + b_hh[g];
            wa_[q][jc]   = w_ih[g * 2];
            wb_[q][jc]   = w_ih[g * 2 + 1];
        }
    }

    // int8 B fragments: col g = q*64 + 8w + grp; kt in {0,1}, reg k-offset 16
    unsigned bf[4][2][2];
    #pragma unroll
    for (int q = 0; q < 4; ++q) {
        const float* wr = &w_hh[(size_t)(q * 64 + wid * 8 + grp) * 64];
        #pragma unroll
        for (int kt = 0; kt < 2; ++kt) {
            #pragma unroll
            for (int rg = 0; rg < 2; ++rg) {
                unsigned v = 0;
                #pragma unroll
                for (int j = 0; j < 4; ++j) {
                    int k = 32 * kt + 16 * rg + 4 * tig + j;
                    int qv = __float2int_rn(wr[k] * wscale);
                    qv = max(-127, min(127, qv));
                    v |= ((unsigned)(qv & 0xFF)) << (8 * j);
                }
                bf[q][kt][rg] = v;
            }
        }
    }

    const __half2 h05 = __float2half2_rn(0.5f);
    __half2 creg[4];
    #pragma unroll
    for (int r = 0; r < 4; ++r) creg[r] = __float2half2_rn(0.f);

    __syncthreads();

    for (int t = 0; t < Tt; ++t) {
        const unsigned char* rb8 = hsh8[t & 1];
        unsigned char*       wb8 = hsh8[(t + 1) & 1];

        int d[4][2][4];
        #pragma unroll
        for (int q = 0; q < 4; ++q)
            #pragma unroll
            for (int m = 0; m < 2; ++m)
                #pragma unroll
                for (int e = 0; e < 4; ++e) d[q][m][e] = 0;

        // ---- int8 MMAs: h @ W_hh^T, 2 M-tiles x 2 k32-tiles -------
        #pragma unroll
        for (int kt = 0; kt < 2; ++kt) {
            #pragma unroll
            for (int m = 0; m < 2; ++m) {
                const unsigned char* r0 = rb8 + (size_t)HROW * (grp + 16 * m) + 32 * kt + 4 * tig;
                const unsigned char* r1 = rb8 + (size_t)HROW * (grp + 8 + 16 * m) + 32 * kt + 4 * tig;
                unsigned a0 = *(const unsigned*)r0;
                unsigned a1 = *(const unsigned*)r1;
                unsigned a2 = *(const unsigned*)(r0 + 16);
                unsigned a3 = *(const unsigned*)(r1 + 16);
                #pragma unroll
                for (int q = 0; q < 4; ++q)
                    mma_s8(d[q][m][0], d[q][m][1], d[q][m][2], d[q][m][3],
                           a0, a1, a2, a3, bf[q][kt][0], bf[q][kt][1]);
            }
        }

        // ---- dequant + exact init + fp16x2 cell update ------------
        #pragma unroll
        for (int r = 0; r < 4; ++r) {
            int row = grp + 8 * r;
            int m_ = r >> 1;
            int pb = (r & 1) * 2;
            float2 xr = xshf[t * NB + row];
            float gf[4][2];
            #pragma unroll
            for (int q = 0; q < 4; ++q) {
                gf[q][0] = fmaf((float)d[q][m_][pb],     sdq,
                           fmaf(wb_[q][0], xr.y, fmaf(wa_[q][0], xr.x, bias_[q][0])));
                gf[q][1] = fmaf((float)d[q][m_][pb + 1], sdq,
                           fmaf(wb_[q][1], xr.y, fmaf(wa_[q][1], xr.x, bias_[q][1])));
            }
            __half2 i2 = sig2(pack2(gf[0][0], gf[0][1]), h05);
            __half2 f2 = sig2(pack2(gf[1][0], gf[1][1]), h05);
            __half2 g2 = u2h(tanh2(pack2(gf[2][0], gf[2][1])));
            __half2 o2 = sig2(pack2(gf[3][0], gf[3][1]), h05);
            creg[r] = __hfma2(f2, creg[r], __hmul2(i2, g2));
            __half2 hh = __hmul2(o2, u2h(tanh2(h2u(creg[r]))));
            if (t == Tt - 1) {
                *(float2*)&g_h[(size_t)(base + row) * 64 + j0] =
                    make_float2(__low2float(hh), __high2float(hh));
            } else {
                float2 hf = __half22float2(hh);
                int q0 = __float2int_rn(hf.x * 127.f);
                int q1 = __float2int_rn(hf.y * 127.f);
                *(unsigned short*)(wb8 + (size_t)HROW * row + j0) =
                    (unsigned short)((q0 & 0xFF) | ((q1 & 0xFF) << 8));
            }
        }
        __syncthreads();   // wbuf visible before next step's reads
    }
}

// ==================== GAT: transform + attention (fused) ===========
// Thread owns word p = (head, dim pair); 4 nodes of the 16-node tile.
// Warp (ng, head) reduces attention partials with shfl (fp32, pre-round).
__global__ void __launch_bounds__(256)
xform_kernel(const float* __restrict__ gat_w, const float* __restrict__ att_src,
             const float* __restrict__ att_dst)
{
    __shared__ float gwt[64 * 128];   // gat_w transposed [k][hg]
    __shared__ float hs[16 * 64];     // 16 nodes
    const int tid  = threadIdx.x;
    const int base = blockIdx.x * 16;

    for (int i = tid; i < 128 * 64; i += 256) {
        int hg = i >> 6, k = i & 63;
        gwt[k * 128 + hg] = gat_w[i];
    }
    for (int i = tid; i < 16 * 64; i += 256) hs[i] = g_h[(size_t)base * 64 + i];
    __syncthreads();

    const int p = tid & 63, ng = tid >> 6;   // word p; nodes ng*4..ng*4+3
    float a0[4] = {0, 0, 0, 0}, a1[4] = {0, 0, 0, 0};
    #pragma unroll 4
    for (int k = 0; k < 64; ++k) {
        float w0 = gwt[k * 128 + 2 * p];
        float w1 = gwt[k * 128 + 2 * p + 1];
        #pragma unroll
        for (int i = 0; i < 4; ++i) {
            float h = hs[(ng * 4 + i) * 64 + k];
            a0[i] = fmaf(h, w0, a0[i]);
            a1[i] = fmaf(h, w1, a1[i]);
        }
    }
    #pragma unroll
    for (int i = 0; i < 4; ++i) {
        size_t n = base + ng * 4 + i;
        g_xh2[n * 64 + p]  = __floats2half2_rn(a0[i], a1[i]);
        g_acc2[n * 64 + p] = __float2half2_rn(0.f);
    }

    // attention partials: att layout [head][64] -> float2 index == p
    float2 as = ((const float2*)att_src)[p];
    float2 ad = ((const float2*)att_dst)[p];
    float ps[4], pd[4];
    #pragma unroll
    for (int i = 0; i < 4; ++i) {
        ps[i] = a0[i] * as.x + a1[i] * as.y;
        pd[i] = a0[i] * ad.x + a1[i] * ad.y;
    }
    // warp = (ng, head): full-warp reduction
    const int lane = tid & 31, head = (tid >> 5) & 1;
    #pragma unroll
    for (int off = 16; off; off >>= 1) {
        #pragma unroll
        for (int i = 0; i < 4; ++i) {
            ps[i] += __shfl_down_sync(0xffffffffu, ps[i], off);
            pd[i] += __shfl_down_sync(0xffffffffu, pd[i], off);
        }
    }
    if (lane == 0) {
        #pragma unroll
        for (int i = 0; i < 4; ++i) {
            int n = base + ng * 4 + i;
            g_asrc[n * 2 + head] = ps[i];
            g_adst[n * 2 + head] = pd[i];
            g_z[n * 2 + head]    = 0.f;
        }
    }
}

// ==================== GAT: exp-sum + weighted messages (fp16) ======
__global__ void __launch_bounds__(256)
edge_sum_kernel(const int* __restrict__ ei32)
{
    int w    = (blockIdx.x * 256 + threadIdx.x) >> 5;
    int lane = threadIdx.x & 31;
    if (w >= ETOT) return;
    const int st = g_estride, of = g_eoff;
    int s, d;
    if (w < Ee) { s = ei32[(size_t)w * st]; d = ei32[(size_t)of + (size_t)w * st]; }
    else        { s = d = w - Ee; }
    float e0 = g_asrc[s * 2]     + g_adst[d * 2];
    float e1 = g_asrc[s * 2 + 1] + g_adst[d * 2 + 1];
    e0 = e0 > 0.f ? e0 : 0.2f * e0;
    e1 = e1 > 0.f ? e1 : 0.2f * e1;
    float w0 = __expf(e0);
    float w1 = __expf(e1);
    if (lane == 0) {
        atomicAdd(&g_z[d * 2],     w0);
        atomicAdd(&g_z[d * 2 + 1], w1);
    }
    __half2 c0 = __float2half2_rn(w0);
    __half2 c1 = __float2half2_rn(w1);
    __half2 x0 = g_xh2[(size_t)s * 64 + lane];
    __half2 x1 = g_xh2[(size_t)s * 64 + 32 + lane];
    atomicAdd(&g_acc2[(size_t)d * 64 + lane],      __hmul2(x0, c0));
    atomicAdd(&g_acc2[(size_t)d * 64 + 32 + lane], __hmul2(x1, c1));
}

// ==================== finalize: mean heads + relu + linear + sigmoid
__global__ void __launch_bounds__(256)
final_kernel(const float* __restrict__ gat_b, const float* __restrict__ lin_w,
             const float* __restrict__ lin_b, float* __restrict__ out)
{
    int n    = (blockIdx.x * 256 + threadIdx.x) >> 5;
    int lane = threadIdx.x & 31;
    if (n >= Nn) return;
    float r0 = 0.5f / g_z[n * 2];
    float r1 = 0.5f / g_z[n * 2 + 1];
    float2 a0 = __half22float2(g_acc2[(size_t)n * 64 + lane]);
    float2 a1 = __half22float2(g_acc2[(size_t)n * 64 + 32 + lane]);
    float2 gb = ((const float2*)gat_b)[lane];
    float v0 = a0.x * r0 + a1.x * r1 + gb.x;
    float v1 = a0.y * r0 + a1.y * r1 + gb.y;
    v0 = v0 > 0.f ? v0 : 0.f;
    v1 = v1 > 0.f ? v1 : 0.f;
    float2 l0 = ((const float2*)lin_w)[lane];
    float2 l1 = ((const float2*)lin_w)[32 + lane];
    float y0 = v0 * l0.x + v1 * l0.y;
    float y1 = v0 * l1.x + v1 * l1.y;
    #pragma unroll
    for (int off = 16; off; off >>= 1) {
        y0 += __shfl_down_sync(0xffffffffu, y0, off);
        y1 += __shfl_down_sync(0xffffffffu, y1, off);
    }
    if (lane == 0) {
        out[n * 2]     = 1.f / (1.f + __expf(-(y0 + lin_b[0])));
        out[n * 2 + 1] = 1.f / (1.f + __expf(-(y1 + lin_b[1])));
    }
}

// ==================== launch =======================================
extern "C" void kernel_launch(void* const* d_in, const int* in_sizes, int n_in,
                              void* d_out, int out_size)
{
    const float* x       = (const float*)d_in[0];
    const int*   ei32    = (const int*)d_in[1];     // int32 view; probe decides layout
    const float* w_ih    = (const float*)d_in[2];
    const float* w_hh    = (const float*)d_in[3];
    const float* b_ih    = (const float*)d_in[4];
    const float* b_hh    = (const float*)d_in[5];
    const float* gat_w   = (const float*)d_in[6];
    const float* att_src = (const float*)d_in[7];
    const float* att_dst = (const float*)d_in[8];
    const float* gat_b   = (const float*)d_in[9];
    const float* lin_w   = (const float*)d_in[10];
    const float* lin_b   = (const float*)d_in[11];
    float*       out     = (float*)d_out;

    detect_kernel<<<1, 256>>>(ei32, w_hh);
    lstm_kernel<<<Nn / NB, 256>>>(x, w_ih, w_hh, b_ih, b_hh);
    xform_kernel<<<Nn / 16, 256>>>(gat_w, att_src, att_dst);
    edge_sum_kernel<<<(ETOT + 7) / 8, 256>>>(ei32);
    final_kernel<<<Nn / 8, 256>>>(gat_b, lin_w, lin_b, out);
}

// round 12
// speedup vs baseline: 1.7580x; 1.7580x over previous
#include <cuda_runtime.h>
#include <cuda_fp16.h>
#include <math.h>

// Problem constants
#define Nn   100000
#define Tt   64
#define Ee   1000000
#define ETOT (Ee + Nn)    // edges + self loops
#define NB   32           // nodes per LSTM block
#define HW   36           // hsh row stride in 32-bit words
#define HS   (NB * HW)    // one h buffer in words

// -------- scratch (device globals; no allocations allowed) ----------
__device__ float   g_h[Nn * 64];     // LSTM final hidden
__device__ __half2 g_xh2[Nn * 64];   // GAT features, word p = (head p/32, dims 2p%64)
__device__ __half2 g_acc2[Nn * 64];  // weighted message accumulator (fp16x2)
__device__ float   g_asrc[Nn * 2];
__device__ float   g_adst[Nn * 2];
__device__ float   g_z[Nn * 2];      // segment sum (fp32)
__device__ int     g_estride;        // 1 if edge_index is int32, 2 if int64
__device__ int     g_eoff;           // offset (in int32 words) of dst row

// ==================== edge dtype probe =============================
__global__ void detect_kernel(const int* __restrict__ ei32)
{
    if (threadIdx.x == 0 && blockIdx.x == 0) {
        bool all0 = true;
        #pragma unroll
        for (int i = 1; i < 64; i += 2) all0 &= (ei32[i] == 0);
        g_estride = all0 ? 2 : 1;
        g_eoff    = all0 ? 2 * Ee : Ee;
    }
}

// ==================== helpers ======================================
__device__ __forceinline__ unsigned tanh2(unsigned x)
{
    unsigned y;
    asm("tanh.approx.f16x2 %0, %1;" : "=r"(y) : "r"(x));
    return y;
}
__device__ __forceinline__ __half2 u2h(unsigned u) { return *reinterpret_cast<__half2*>(&u); }
__device__ __forceinline__ unsigned h2u(__half2 h) { return *reinterpret_cast<unsigned*>(&h); }

// fp16x2 sigmoid: 0.5 + 0.5*tanh(0.5*x)
__device__ __forceinline__ __half2 sig2(unsigned u, __half2 half05)
{
    __half2 x = __hmul2(u2h(u), half05);
    return __hfma2(u2h(tanh2(h2u(x))), half05, half05);
}

__device__ __forceinline__ unsigned f2h2u(float a, float b)
{
    __half2 h = __floats2half2_rn(a, b);
    return *reinterpret_cast<unsigned*>(&h);
}

// m16n8k16, fp16 in / fp16 accum. D regs = 2x fp16x2.
__device__ __forceinline__ void mma_f16acc(unsigned& c0, unsigned& c1,
                                           unsigned a0, unsigned a1, unsigned a2, unsigned a3,
                                           unsigned b0, unsigned b1)
{
    asm("mma.sync.aligned.m16n8k16.row.col.f16.f16.f16.f16 "
        "{%0,%1}, {%2,%3,%4,%5}, {%6,%7}, {%0,%1};"
        : "+r"(c0), "+r"(c1)
        : "r"(a0), "r"(a1), "r"(a2), "r"(a3), "r"(b0), "r"(b1));
}

// ==================== LSTM (all-fp16, 32 nodes/block) ==============
// R10 configuration: fastest verified LSTM (fp16 m16n8k16, fp16 accum,
// B in registers reused by two M-tiles, h double-buffered, one
// barrier per step).
__global__ void __launch_bounds__(256, 2)
lstm_kernel(const float* __restrict__ x, const float* __restrict__ w_ih,
            const float* __restrict__ w_hh, const float* __restrict__ b_ih,
            const float* __restrict__ b_hh)
{
    __shared__ unsigned xsh[Tt * NB * 2];   // broadcast half2 per (t, n, d)
    __shared__ unsigned hsh[2 * HS];        // double-buffered h, fp16x2 words

    const int tid  = threadIdx.x;
    const int base = blockIdx.x * NB;
    const int wid  = tid >> 5, lane = tid & 31;
    const int grp  = lane >> 2, tig = lane & 3;

    for (int i = tid; i < NB * Tt * 2; i += 256) {
        int n = i >> 7;
        int r = i & 127;
        float v = x[(size_t)(base + n) * 128 + r];
        xsh[(r >> 1) * (NB * 2) + n * 2 + (r & 1)] = h2u(__float2half2_rn(v));
    }
    for (int i = tid; i < 2 * HS; i += 256) hsh[i] = 0u;

    const int j0 = wid * 8 + 2 * tig;

    unsigned bias2[4], wa2[4], wb2[4];
    #pragma unroll
    for (int q = 0; q < 4; ++q) {
        int g = q * 64 + j0;
        bias2[q] = f2h2u(b_ih[g] + b_hh[g], b_ih[g + 1] + b_hh[g + 1]);
        wa2[q]   = f2h2u(w_ih[g * 2],     w_ih[(g + 1) * 2]);
        wb2[q]   = f2h2u(w_ih[g * 2 + 1], w_ih[(g + 1) * 2 + 1]);
    }

    unsigned bf[4][4][2];
    #pragma unroll
    for (int q = 0; q < 4; ++q) {
        const float* wr = &w_hh[(size_t)(q * 64 + wid * 8 + grp) * 64];
        #pragma unroll
        for (int kt = 0; kt < 4; ++kt) {
            int k = kt * 16 + 2 * tig;
            bf[q][kt][0] = f2h2u(wr[k],     wr[k + 1]);
            bf[q][kt][1] = f2h2u(wr[k + 8], wr[k + 9]);
        }
    }

    const int rp[4] = { grp * HW + tig,        (grp + 8) * HW + tig,
                        (grp + 16) * HW + tig, (grp + 24) * HW + tig };
    const int sp[4] = { grp * HW + wid * 4 + tig,        (grp + 8) * HW + wid * 4 + tig,
                        (grp + 16) * HW + wid * 4 + tig, (grp + 24) * HW + wid * 4 + tig };

    const __half2 half05 = __float2half2_rn(0.5f);
    __half2 creg[4];
    #pragma unroll
    for (int r = 0; r < 4; ++r) creg[r] = __float2half2_rn(0.f);

    __syncthreads();

    for (int t = 0; t < Tt; ++t) {
        const unsigned* rb   = &hsh[(t & 1) * HS];
        unsigned*       wbuf = &hsh[((t + 1) & 1) * HS];

        unsigned xl[4], xh[4];
        #pragma unroll
        for (int m = 0; m < 4; ++m) {
            int n = grp + 8 * m;
            xl[m] = xsh[t * (NB * 2) + n * 2];
            xh[m] = xsh[t * (NB * 2) + n * 2 + 1];
        }
        unsigned c[4][4];
        #pragma unroll
        for (int q = 0; q < 4; ++q) {
            #pragma unroll
            for (int m = 0; m < 4; ++m)
                c[q][m] = h2u(__hfma2(u2h(wb2[q]), u2h(xh[m]),
                              __hfma2(u2h(wa2[q]), u2h(xl[m]), u2h(bias2[q]))));
        }
        #pragma unroll
        for (int kt = 0; kt < 4; ++kt) {
            unsigned a0 = rb[rp[0] + kt * 8];
            unsigned a1 = rb[rp[1] + kt * 8];
            unsigned a2 = rb[rp[0] + kt * 8 + 4];
            unsigned a3 = rb[rp[1] + kt * 8 + 4];
            unsigned a4 = rb[rp[2] + kt * 8];
            unsigned a5 = rb[rp[3] + kt * 8];
            unsigned a6 = rb[rp[2] + kt * 8 + 4];
            unsigned a7 = rb[rp[3] + kt * 8 + 4];
            #pragma unroll
            for (int q = 0; q < 4; ++q) {
                mma_f16acc(c[q][0], c[q][1], a0, a1, a2, a3,
                           bf[q][kt][0], bf[q][kt][1]);
                mma_f16acc(c[q][2], c[q][3], a4, a5, a6, a7,
                           bf[q][kt][0], bf[q][kt][1]);
            }
        }

        #pragma unroll
        for (int r = 0; r < 4; ++r) {
            __half2 i2 = sig2(c[0][r], half05);
            __half2 f2 = sig2(c[1][r], half05);
            __half2 g2 = u2h(tanh2(c[2][r]));
            __half2 o2 = sig2(c[3][r], half05);
            creg[r] = __hfma2(f2, creg[r], __hmul2(i2, g2));
            __half2 hh = __hmul2(o2, u2h(tanh2(h2u(creg[r]))));
            if (t == Tt - 1) {
                int row = grp + 8 * r;
                *(float2*)&g_h[(size_t)(base + row) * 64 + j0] =
                    make_float2(__low2float(hh), __high2float(hh));
            } else {
                wbuf[sp[r]] = h2u(hh);
            }
        }
        __syncthreads();
    }
}

// ==================== GAT: transform + attention (fused) ===========
// Thread owns word p = (head, dim pair); 4 nodes of the 16-node tile.
// Attention partials reduced per-warp on pre-rounded fp32 xh.
__global__ void __launch_bounds__(256)
xform_kernel(const float* __restrict__ gat_w, const float* __restrict__ att_src,
             const float* __restrict__ att_dst)
{
    __shared__ float gwt[64 * 128];   // gat_w transposed [k][hg]
    __shared__ float hs[16 * 64];     // 16 nodes
    const int tid  = threadIdx.x;
    const int base = blockIdx.x * 16;

    for (int i = tid; i < 128 * 64; i += 256) {
        int hg = i >> 6, k = i & 63;
        gwt[k * 128 + hg] = gat_w[i];
    }
    for (int i = tid; i < 16 * 64; i += 256) hs[i] = g_h[(size_t)base * 64 + i];
    __syncthreads();

    const int p = tid & 63, ng = tid >> 6;   // word p; nodes ng*4..ng*4+3
    float a0[4] = {0, 0, 0, 0}, a1[4] = {0, 0, 0, 0};
    #pragma unroll 4
    for (int k = 0; k < 64; ++k) {
        float w0 = gwt[k * 128 + 2 * p];
        float w1 = gwt[k * 128 + 2 * p + 1];
        #pragma unroll
        for (int i = 0; i < 4; ++i) {
            float h = hs[(ng * 4 + i) * 64 + k];
            a0[i] = fmaf(h, w0, a0[i]);
            a1[i] = fmaf(h, w1, a1[i]);
        }
    }
    #pragma unroll
    for (int i = 0; i < 4; ++i) {
        size_t n = base + ng * 4 + i;
        g_xh2[n * 64 + p]  = __floats2half2_rn(a0[i], a1[i]);
        g_acc2[n * 64 + p] = __float2half2_rn(0.f);
    }

    // attention partials: att layout [head][64] -> float2 index == p
    float2 as = ((const float2*)att_src)[p];
    float2 ad = ((const float2*)att_dst)[p];
    float ps[4], pd[4];
    #pragma unroll
    for (int i = 0; i < 4; ++i) {
        ps[i] = a0[i] * as.x + a1[i] * as.y;
        pd[i] = a0[i] * ad.x + a1[i] * ad.y;
    }
    // warp = (ng, head): full-warp reduction
    const int lane = tid & 31, head = (tid >> 5) & 1;
    #pragma unroll
    for (int off = 16; off; off >>= 1) {
        #pragma unroll
        for (int i = 0; i < 4; ++i) {
            ps[i] += __shfl_down_sync(0xffffffffu, ps[i], off);
            pd[i] += __shfl_down_sync(0xffffffffu, pd[i], off);
        }
    }
    if (lane == 0) {
        #pragma unroll
        for (int i = 0; i < 4; ++i) {
            int n = base + ng * 4 + i;
            g_asrc[n * 2 + head] = ps[i];
            g_adst[n * 2 + head] = pd[i];
            g_z[n * 2 + head]    = 0.f;
        }
    }
}

// ==================== GAT: exp-sum + weighted messages (fp16) ======
// Logits are O(0.05): softmax without max-subtraction is exact-safe.
__global__ void __launch_bounds__(256)
edge_sum_kernel(const int* __restrict__ ei32)
{
    int w    = (blockIdx.x * 256 + threadIdx.x) >> 5;
    int lane = threadIdx.x & 31;
    if (w >= ETOT) return;
    const int st = g_estride, of = g_eoff;
    int s, d;
    if (w < Ee) { s = ei32[(size_t)w * st]; d = ei32[(size_t)of + (size_t)w * st]; }
    else        { s = d = w - Ee; }
    float e0 = g_asrc[s * 2]     + g_adst[d * 2];
    float e1 = g_asrc[s * 2 + 1] + g_adst[d * 2 + 1];
    e0 = e0 > 0.f ? e0 : 0.2f * e0;
    e1 = e1 > 0.f ? e1 : 0.2f * e1;
    float w0 = __expf(e0);
    float w1 = __expf(e1);
    if (lane == 0) {
        atomicAdd(&g_z[d * 2],     w0);
        atomicAdd(&g_z[d * 2 + 1], w1);
    }
    __half2 c0 = __float2half2_rn(w0);
    __half2 c1 = __float2half2_rn(w1);
    __half2 x0 = g_xh2[(size_t)s * 64 + lane];
    __half2 x1 = g_xh2[(size_t)s * 64 + 32 + lane];
    atomicAdd(&g_acc2[(size_t)d * 64 + lane],      __hmul2(x0, c0));
    atomicAdd(&g_acc2[(size_t)d * 64 + 32 + lane], __hmul2(x1, c1));
}

// ==================== finalize: mean heads + relu + linear + sigmoid
__global__ void __launch_bounds__(256)
final_kernel(const float* __restrict__ gat_b, const float* __restrict__ lin_w,
             const float* __restrict__ lin_b, float* __restrict__ out)
{
    int n    = (blockIdx.x * 256 + threadIdx.x) >> 5;
    int lane = threadIdx.x & 31;
    if (n >= Nn) return;
    float r0 = 0.5f / g_z[n * 2];
    float r1 = 0.5f / g_z[n * 2 + 1];
    float2 a0 = __half22float2(g_acc2[(size_t)n * 64 + lane]);
    float2 a1 = __half22float2(g_acc2[(size_t)n * 64 + 32 + lane]);
    float2 gb = ((const float2*)gat_b)[lane];
    float v0 = a0.x * r0 + a1.x * r1 + gb.x;
    float v1 = a0.y * r0 + a1.y * r1 + gb.y;
    v0 = v0 > 0.f ? v0 : 0.f;
    v1 = v1 > 0.f ? v1 : 0.f;
    float2 l0 = ((const float2*)lin_w)[lane];
    float2 l1 = ((const float2*)lin_w)[32 + lane];
    float y0 = v0 * l0.x + v1 * l0.y;
    float y1 = v0 * l1.x + v1 * l1.y;
    #pragma unroll
    for (int off = 16; off; off >>= 1) {
        y0 += __shfl_down_sync(0xffffffffu, y0, off);
        y1 += __shfl_down_sync(0xffffffffu, y1, off);
    }
    if (lane == 0) {
        out[n * 2]     = 1.f / (1.f + __expf(-(y0 + lin_b[0])));
        out[n * 2 + 1] = 1.f / (1.f + __expf(-(y1 + lin_b[1])));
    }
}

// ==================== launch =======================================
extern "C" void kernel_launch(void* const* d_in, const int* in_sizes, int n_in,
                              void* d_out, int out_size)
{
    const float* x       = (const float*)d_in[0];
    const int*   ei32    = (const int*)d_in[1];     // int32 view; probe decides layout
    const float* w_ih    = (const float*)d_in[2];
    const float* w_hh    = (const float*)d_in[3];
    const float* b_ih    = (const float*)d_in[4];
    const float* b_hh    = (const float*)d_in[5];
    const float* gat_w   = (const float*)d_in[6];
    const float* att_src = (const float*)d_in[7];
    const float* att_dst = (const float*)d_in[8];
    const float* gat_b   = (const float*)d_in[9];
    const float* lin_w   = (const float*)d_in[10];
    const float* lin_b   = (const float*)d_in[11];
    float*       out     = (float*)d_out;

    detect_kernel<<<1, 32>>>(ei32);
    lstm_kernel<<<Nn / NB, 256>>>(x, w_ih, w_hh, b_ih, b_hh);
    xform_kernel<<<Nn / 16, 256>>>(gat_w, att_src, att_dst);
    edge_sum_kernel<<<(ETOT + 7) / 8, 256>>>(ei32);
    final_kernel<<<Nn / 8, 256>>>(gat_b, lin_w, lin_b, out);
}

// round 13
// speedup vs baseline: 1.9130x; 1.0882x over previous
#include <cuda_runtime.h>
#include <cuda_fp16.h>
#include <math.h>

// Problem constants
#define Nn   100000
#define Tt   64
#define Ee   1000000
#define ETOT (Ee + Nn)    // edges + self loops
#define NB   32           // nodes per LSTM block
#define HW   36           // hsh row stride in 32-bit words
#define HS   (NB * HW)    // one h buffer in words

// -------- scratch (device globals; no allocations allowed) ----------
__device__ float   g_h[Nn * 64];     // LSTM final hidden
__device__ __half2 g_xh2[Nn * 64];   // GAT features, word p = (head p/32, dims 2p%64)
__device__ __half2 g_acc2[Nn * 64];  // weighted message accumulator (fp16x2)
__device__ float   g_asrc[Nn * 2];
__device__ float   g_adst[Nn * 2];
__device__ float   g_z[Nn * 2];      // segment sum (fp32)
__device__ int     g_estride;        // 1 if edge_index is int32, 2 if int64
__device__ int     g_eoff;           // offset (in int32 words) of dst row

// ==================== edge dtype probe =============================
__global__ void detect_kernel(const int* __restrict__ ei32)
{
    if (threadIdx.x == 0 && blockIdx.x == 0) {
        bool all0 = true;
        #pragma unroll
        for (int i = 1; i < 64; i += 2) all0 &= (ei32[i] == 0);
        g_estride = all0 ? 2 : 1;
        g_eoff    = all0 ? 2 * Ee : Ee;
    }
}

// ==================== helpers ======================================
__device__ __forceinline__ unsigned tanh2(unsigned x)
{
    unsigned y;
    asm("tanh.approx.f16x2 %0, %1;" : "=r"(y) : "r"(x));
    return y;
}
__device__ __forceinline__ __half2 u2h(unsigned u) { return *reinterpret_cast<__half2*>(&u); }
__device__ __forceinline__ unsigned h2u(__half2 h) { return *reinterpret_cast<unsigned*>(&h); }

// fp16x2 sigmoid: 0.5 + 0.5*tanh(0.5*x)
__device__ __forceinline__ __half2 sig2(unsigned u, __half2 half05)
{
    __half2 x = __hmul2(u2h(u), half05);
    return __hfma2(u2h(tanh2(h2u(x))), half05, half05);
}

__device__ __forceinline__ unsigned f2h2u(float a, float b)
{
    __half2 h = __floats2half2_rn(a, b);
    return *reinterpret_cast<unsigned*>(&h);
}

// m16n8k16, fp16 in / fp16 accum. D regs = 2x fp16x2.
__device__ __forceinline__ void mma_f16acc(unsigned& c0, unsigned& c1,
                                           unsigned a0, unsigned a1, unsigned a2, unsigned a3,
                                           unsigned b0, unsigned b1)
{
    asm("mma.sync.aligned.m16n8k16.row.col.f16.f16.f16.f16 "
        "{%0,%1}, {%2,%3,%4,%5}, {%6,%7}, {%0,%1};"
        : "+r"(c0), "+r"(c1)
        : "r"(a0), "r"(a1), "r"(a2), "r"(a3), "r"(b0), "r"(b1));
}

// ==================== LSTM (all-fp16, 32 nodes/block) ==============
// Fastest verified LSTM: at the fallback-HMMA throughput ceiling with
// minimum MMA instruction count. Unchanged.
__global__ void __launch_bounds__(256, 2)
lstm_kernel(const float* __restrict__ x, const float* __restrict__ w_ih,
            const float* __restrict__ w_hh, const float* __restrict__ b_ih,
            const float* __restrict__ b_hh)
{
    __shared__ unsigned xsh[Tt * NB * 2];   // broadcast half2 per (t, n, d)
    __shared__ unsigned hsh[2 * HS];        // double-buffered h, fp16x2 words

    const int tid  = threadIdx.x;
    const int base = blockIdx.x * NB;
    const int wid  = tid >> 5, lane = tid & 31;
    const int grp  = lane >> 2, tig = lane & 3;

    for (int i = tid; i < NB * Tt * 2; i += 256) {
        int n = i >> 7;
        int r = i & 127;
        float v = x[(size_t)(base + n) * 128 + r];
        xsh[(r >> 1) * (NB * 2) + n * 2 + (r & 1)] = h2u(__float2half2_rn(v));
    }
    for (int i = tid; i < 2 * HS; i += 256) hsh[i] = 0u;

    const int j0 = wid * 8 + 2 * tig;

    unsigned bias2[4], wa2[4], wb2[4];
    #pragma unroll
    for (int q = 0; q < 4; ++q) {
        int g = q * 64 + j0;
        bias2[q] = f2h2u(b_ih[g] + b_hh[g], b_ih[g + 1] + b_hh[g + 1]);
        wa2[q]   = f2h2u(w_ih[g * 2],     w_ih[(g + 1) * 2]);
        wb2[q]   = f2h2u(w_ih[g * 2 + 1], w_ih[(g + 1) * 2 + 1]);
    }

    unsigned bf[4][4][2];
    #pragma unroll
    for (int q = 0; q < 4; ++q) {
        const float* wr = &w_hh[(size_t)(q * 64 + wid * 8 + grp) * 64];
        #pragma unroll
        for (int kt = 0; kt < 4; ++kt) {
            int k = kt * 16 + 2 * tig;
            bf[q][kt][0] = f2h2u(wr[k],     wr[k + 1]);
            bf[q][kt][1] = f2h2u(wr[k + 8], wr[k + 9]);
        }
    }

    const int rp[4] = { grp * HW + tig,        (grp + 8) * HW + tig,
                        (grp + 16) * HW + tig, (grp + 24) * HW + tig };
    const int sp[4] = { grp * HW + wid * 4 + tig,        (grp + 8) * HW + wid * 4 + tig,
                        (grp + 16) * HW + wid * 4 + tig, (grp + 24) * HW + wid * 4 + tig };

    const __half2 half05 = __float2half2_rn(0.5f);
    __half2 creg[4];
    #pragma unroll
    for (int r = 0; r < 4; ++r) creg[r] = __float2half2_rn(0.f);

    __syncthreads();

    for (int t = 0; t < Tt; ++t) {
        const unsigned* rb   = &hsh[(t & 1) * HS];
        unsigned*       wbuf = &hsh[((t + 1) & 1) * HS];

        unsigned xl[4], xh[4];
        #pragma unroll
        for (int m = 0; m < 4; ++m) {
            int n = grp + 8 * m;
            xl[m] = xsh[t * (NB * 2) + n * 2];
            xh[m] = xsh[t * (NB * 2) + n * 2 + 1];
        }
        unsigned c[4][4];
        #pragma unroll
        for (int q = 0; q < 4; ++q) {
            #pragma unroll
            for (int m = 0; m < 4; ++m)
                c[q][m] = h2u(__hfma2(u2h(wb2[q]), u2h(xh[m]),
                              __hfma2(u2h(wa2[q]), u2h(xl[m]), u2h(bias2[q]))));
        }
        #pragma unroll
        for (int kt = 0; kt < 4; ++kt) {
            unsigned a0 = rb[rp[0] + kt * 8];
            unsigned a1 = rb[rp[1] + kt * 8];
            unsigned a2 = rb[rp[0] + kt * 8 + 4];
            unsigned a3 = rb[rp[1] + kt * 8 + 4];
            unsigned a4 = rb[rp[2] + kt * 8];
            unsigned a5 = rb[rp[3] + kt * 8];
            unsigned a6 = rb[rp[2] + kt * 8 + 4];
            unsigned a7 = rb[rp[3] + kt * 8 + 4];
            #pragma unroll
            for (int q = 0; q < 4; ++q) {
                mma_f16acc(c[q][0], c[q][1], a0, a1, a2, a3,
                           bf[q][kt][0], bf[q][kt][1]);
                mma_f16acc(c[q][2], c[q][3], a4, a5, a6, a7,
                           bf[q][kt][0], bf[q][kt][1]);
            }
        }

        #pragma unroll
        for (int r = 0; r < 4; ++r) {
            __half2 i2 = sig2(c[0][r], half05);
            __half2 f2 = sig2(c[1][r], half05);
            __half2 g2 = u2h(tanh2(c[2][r]));
            __half2 o2 = sig2(c[3][r], half05);
            creg[r] = __hfma2(f2, creg[r], __hmul2(i2, g2));
            __half2 hh = __hmul2(o2, u2h(tanh2(h2u(creg[r]))));
            if (t == Tt - 1) {
                int row = grp + 8 * r;
                *(float2*)&g_h[(size_t)(base + row) * 64 + j0] =
                    make_float2(__low2float(hh), __high2float(hh));
            } else {
                wbuf[sp[r]] = h2u(hh);
            }
        }
        __syncthreads();
    }
}

// ==================== GAT: transform + attention (fused) ===========
__global__ void __launch_bounds__(256)
xform_kernel(const float* __restrict__ gat_w, const float* __restrict__ att_src,
             const float* __restrict__ att_dst)
{
    __shared__ float gwt[64 * 128];   // gat_w transposed [k][hg]
    __shared__ float hs[16 * 64];     // 16 nodes
    const int tid  = threadIdx.x;
    const int base = blockIdx.x * 16;

    for (int i = tid; i < 128 * 64; i += 256) {
        int hg = i >> 6, k = i & 63;
        gwt[k * 128 + hg] = gat_w[i];
    }
    for (int i = tid; i < 16 * 64; i += 256) hs[i] = g_h[(size_t)base * 64 + i];
    __syncthreads();

    const int p = tid & 63, ng = tid >> 6;   // word p; nodes ng*4..ng*4+3
    float a0[4] = {0, 0, 0, 0}, a1[4] = {0, 0, 0, 0};
    #pragma unroll 4
    for (int k = 0; k < 64; ++k) {
        float w0 = gwt[k * 128 + 2 * p];
        float w1 = gwt[k * 128 + 2 * p + 1];
        #pragma unroll
        for (int i = 0; i < 4; ++i) {
            float h = hs[(ng * 4 + i) * 64 + k];
            a0[i] = fmaf(h, w0, a0[i]);
            a1[i] = fmaf(h, w1, a1[i]);
        }
    }
    #pragma unroll
    for (int i = 0; i < 4; ++i) {
        size_t n = base + ng * 4 + i;
        g_xh2[n * 64 + p]  = __floats2half2_rn(a0[i], a1[i]);
        g_acc2[n * 64 + p] = __float2half2_rn(0.f);
    }

    // attention partials: att layout [head][64] -> float2 index == p
    float2 as = ((const float2*)att_src)[p];
    float2 ad = ((const float2*)att_dst)[p];
    float ps[4], pd[4];
    #pragma unroll
    for (int i = 0; i < 4; ++i) {
        ps[i] = a0[i] * as.x + a1[i] * as.y;
        pd[i] = a0[i] * ad.x + a1[i] * ad.y;
    }
    const int lane = tid & 31, head = (tid >> 5) & 1;
    #pragma unroll
    for (int off = 16; off; off >>= 1) {
        #pragma unroll
        for (int i = 0; i < 4; ++i) {
            ps[i] += __shfl_down_sync(0xffffffffu, ps[i], off);
            pd[i] += __shfl_down_sync(0xffffffffu, pd[i], off);
        }
    }
    if (lane == 0) {
        #pragma unroll
        for (int i = 0; i < 4; ++i) {
            int n = base + ng * 4 + i;
            g_asrc[n * 2 + head] = ps[i];
            g_adst[n * 2 + head] = pd[i];
            g_z[n * 2 + head]    = 0.f;
        }
    }
}

// ==================== GAT: exp-sum + weighted messages =============
// Half-warp per edge; each of 16 lanes owns 4 half2 words (16B) and
// issues ONE vectorized red.global.add.v4.f16x2 -> 16 atomics/edge
// instead of 64. Chunks never straddle the head boundary (4 | 32).
__global__ void __launch_bounds__(256)
edge_sum_kernel(const int* __restrict__ ei32)
{
    int e   = (blockIdx.x * 256 + threadIdx.x) >> 4;   // edge per half-warp
    int sub = threadIdx.x & 15;
    if (e >= ETOT) return;
    const int st = g_estride, of = g_eoff;
    int s, d;
    if (e < Ee) { s = ei32[(size_t)e * st]; d = ei32[(size_t)of + (size_t)e * st]; }
    else        { s = d = e - Ee; }

    int head = sub >> 3;   // words 0-31 -> head0, 32-63 -> head1
    float ea = g_asrc[s * 2 + head] + g_adst[d * 2 + head];
    ea = ea > 0.f ? ea : 0.2f * ea;
    float wv = __expf(ea);
    if ((sub & 7) == 0) atomicAdd(&g_z[d * 2 + head], wv);   // sub 0 & 8

    __half2 cc = __float2half2_rn(wv);
    const uint4* xp = (const uint4*)(g_xh2 + (size_t)s * 64) + sub;
    uint4 xv = *xp;
    unsigned m0 = h2u(__hmul2(u2h(xv.x), cc));
    unsigned m1 = h2u(__hmul2(u2h(xv.y), cc));
    unsigned m2 = h2u(__hmul2(u2h(xv.z), cc));
    unsigned m3 = h2u(__hmul2(u2h(xv.w), cc));
    __half2* ap = g_acc2 + (size_t)d * 64 + sub * 4;
    asm volatile("red.global.add.noftz.v4.f16x2 [%0], {%1,%2,%3,%4};"
                 :: "l"(ap), "r"(m0), "r"(m1), "r"(m2), "r"(m3) : "memory");
}

// ==================== finalize: mean heads + relu + linear + sigmoid
__global__ void __launch_bounds__(256)
final_kernel(const float* __restrict__ gat_b, const float* __restrict__ lin_w,
             const float* __restrict__ lin_b, float* __restrict__ out)
{
    int n    = (blockIdx.x * 256 + threadIdx.x) >> 5;
    int lane = threadIdx.x & 31;
    if (n >= Nn) return;
    float r0 = 0.5f / g_z[n * 2];
    float r1 = 0.5f / g_z[n * 2 + 1];
    float2 a0 = __half22float2(g_acc2[(size_t)n * 64 + lane]);
    float2 a1 = __half22float2(g_acc2[(size_t)n * 64 + 32 + lane]);
    float2 gb = ((const float2*)gat_b)[lane];
    float v0 = a0.x * r0 + a1.x * r1 + gb.x;
    float v1 = a0.y * r0 + a1.y * r1 + gb.y;
    v0 = v0 > 0.f ? v0 : 0.f;
    v1 = v1 > 0.f ? v1 : 0.f;
    float2 l0 = ((const float2*)lin_w)[lane];
    float2 l1 = ((const float2*)lin_w)[32 + lane];
    float y0 = v0 * l0.x + v1 * l0.y;
    float y1 = v0 * l1.x + v1 * l1.y;
    #pragma unroll
    for (int off = 16; off; off >>= 1) {
        y0 += __shfl_down_sync(0xffffffffu, y0, off);
        y1 += __shfl_down_sync(0xffffffffu, y1, off);
    }
    if (lane == 0) {
        out[n * 2]     = 1.f / (1.f + __expf(-(y0 + lin_b[0])));
        out[n * 2 + 1] = 1.f / (1.f + __expf(-(y1 + lin_b[1])));
    }
}

// ==================== launch =======================================
extern "C" void kernel_launch(void* const* d_in, const int* in_sizes, int n_in,
                              void* d_out, int out_size)
{
    const float* x       = (const float*)d_in[0];
    const int*   ei32    = (const int*)d_in[1];     // int32 view; probe decides layout
    const float* w_ih    = (const float*)d_in[2];
    const float* w_hh    = (const float*)d_in[3];
    const float* b_ih    = (const float*)d_in[4];
    const float* b_hh    = (const float*)d_in[5];
    const float* gat_w   = (const float*)d_in[6];
    const float* att_src = (const float*)d_in[7];
    const float* att_dst = (const float*)d_in[8];
    const float* gat_b   = (const float*)d_in[9];
    const float* lin_w   = (const float*)d_in[10];
    const float* lin_b   = (const float*)d_in[11];
    float*       out     = (float*)d_out;

    detect_kernel<<<1, 32>>>(ei32);
    lstm_kernel<<<Nn / NB, 256>>>(x, w_ih, w_hh, b_ih, b_hh);
    xform_kernel<<<Nn / 16, 256>>>(gat_w, att_src, att_dst);
    edge_sum_kernel<<<(ETOT + 15) / 16, 256>>>(ei32);
    final_kernel<<<Nn / 8, 256>>>(gat_b, lin_w, lin_b, out);
}

// round 14
// speedup vs baseline: 2.4651x; 1.2886x over previous
#include <cuda_runtime.h>
#include <cuda_fp16.h>
#include <math.h>

// Problem constants
#define Nn   100000
#define Tt   64
#define Ee   1000000
#define ETOT (Ee + Nn)    // edges + self loops
#define NB   32           // nodes per LSTM block
#define HW   36           // hsh row stride in 32-bit words
#define HS   (NB * HW)    // one h buffer in words

// -------- scratch (device globals; no allocations allowed) ----------
__device__ __half2 g_xh2[Nn * 64];   // GAT features, word p = (head p/32, dims 2p%64)
__device__ __half2 g_acc2[Nn * 64];  // weighted message accumulator (fp16x2)
__device__ float   g_asrc[Nn * 2];
__device__ float   g_adst[Nn * 2];
__device__ float   g_z[Nn * 2];      // segment sum (fp32)
__device__ int     g_estride;        // 1 if edge_index is int32, 2 if int64
__device__ int     g_eoff;           // offset (in int32 words) of dst row

// ==================== edge dtype probe =============================
__global__ void detect_kernel(const int* __restrict__ ei32)
{
    if (threadIdx.x == 0 && blockIdx.x == 0) {
        bool all0 = true;
        #pragma unroll
        for (int i = 1; i < 64; i += 2) all0 &= (ei32[i] == 0);
        g_estride = all0 ? 2 : 1;
        g_eoff    = all0 ? 2 * Ee : Ee;
    }
}

// ==================== helpers ======================================
__device__ __forceinline__ unsigned tanh2(unsigned x)
{
    unsigned y;
    asm("tanh.approx.f16x2 %0, %1;" : "=r"(y) : "r"(x));
    return y;
}
__device__ __forceinline__ __half2 u2h(unsigned u) { return *reinterpret_cast<__half2*>(&u); }
__device__ __forceinline__ unsigned h2u(__half2 h) { return *reinterpret_cast<unsigned*>(&h); }

// fp16x2 sigmoid: 0.5 + 0.5*tanh(0.5*x)
__device__ __forceinline__ __half2 sig2(unsigned u, __half2 half05)
{
    __half2 x = __hmul2(u2h(u), half05);
    return __hfma2(u2h(tanh2(h2u(x))), half05, half05);
}

__device__ __forceinline__ unsigned f2h2u(float a, float b)
{
    __half2 h = __floats2half2_rn(a, b);
    return *reinterpret_cast<unsigned*>(&h);
}

// m16n8k16, fp16 in / fp16 accum. D regs = 2x fp16x2 (rows grp, grp+8).
__device__ __forceinline__ void mma_f16acc(unsigned& c0, unsigned& c1,
                                           unsigned a0, unsigned a1, unsigned a2, unsigned a3,
                                           unsigned b0, unsigned b1)
{
    asm("mma.sync.aligned.m16n8k16.row.col.f16.f16.f16.f16 "
        "{%0,%1}, {%2,%3,%4,%5}, {%6,%7}, {%0,%1};"
        : "+r"(c0), "+r"(c1)
        : "r"(a0), "r"(a1), "r"(a2), "r"(a3), "r"(b0), "r"(b1));
}

// m16n8k16, fp16 in / fp32 accum. c0,c1 = (row grp, cols j0,j0+1);
// c2,c3 = (row grp+8, cols j0,j0+1).
__device__ __forceinline__ void mma_f32acc(float& c0, float& c1, float& c2, float& c3,
                                           unsigned a0, unsigned a1, unsigned a2, unsigned a3,
                                           unsigned b0, unsigned b1)
{
    asm("mma.sync.aligned.m16n8k16.row.col.f32.f16.f16.f32 "
        "{%0,%1,%2,%3}, {%4,%5,%6,%7}, {%8,%9}, {%0,%1,%2,%3};"
        : "+f"(c0), "+f"(c1), "+f"(c2), "+f"(c3)
        : "r"(a0), "r"(a1), "r"(a2), "r"(a3), "r"(b0), "r"(b1));
}

// ==================== LSTM + fused GAT transform ===================
// 256 threads = 8 warps, 32 nodes/block. Main loop: fastest verified
// fp16 m16n8k16 recurrence (at fallback-HMMA ceiling). Epilogue:
// final h (already in MMA A-layout in smem) -> xh = h @ gat_w^T via
// 16 fp32-accum MMAs/warp + attention dots, writing g_xh2/g_asrc/
// g_adst directly. No g_h round-trip, no separate xform kernel.
__global__ void __launch_bounds__(256, 2)
lstm_kernel(const float* __restrict__ x, const float* __restrict__ w_ih,
            const float* __restrict__ w_hh, const float* __restrict__ b_ih,
            const float* __restrict__ b_hh, const float* __restrict__ gat_w,
            const float* __restrict__ att_src, const float* __restrict__ att_dst)
{
    __shared__ unsigned xsh[Tt * NB * 2];   // broadcast half2 per (t, n, d)
    __shared__ unsigned hsh[2 * HS];        // double-buffered h, fp16x2 words
    __shared__ float    sm_as[2][NB];       // attention partial sums
    __shared__ float    sm_ad[2][NB];

    const int tid  = threadIdx.x;
    const int base = blockIdx.x * NB;
    const int wid  = tid >> 5, lane = tid & 31;
    const int grp  = lane >> 2, tig = lane & 3;

    for (int i = tid; i < NB * Tt * 2; i += 256) {
        int n = i >> 7;
        int r = i & 127;
        float v = x[(size_t)(base + n) * 128 + r];
        xsh[(r >> 1) * (NB * 2) + n * 2 + (r & 1)] = h2u(__float2half2_rn(v));
    }
    for (int i = tid; i < 2 * HS; i += 256) hsh[i] = 0u;
    if (tid < 64) {
        sm_as[tid >> 5][tid & 31] = 0.f;
        sm_ad[tid >> 5][tid & 31] = 0.f;
    }

    const int j0 = wid * 8 + 2 * tig;

    unsigned bias2[4], wa2[4], wb2[4];
    #pragma unroll
    for (int q = 0; q < 4; ++q) {
        int g = q * 64 + j0;
        bias2[q] = f2h2u(b_ih[g] + b_hh[g], b_ih[g + 1] + b_hh[g + 1]);
        wa2[q]   = f2h2u(w_ih[g * 2],     w_ih[(g + 1) * 2]);
        wb2[q]   = f2h2u(w_ih[g * 2 + 1], w_ih[(g + 1) * 2 + 1]);
    }

    unsigned bf[4][4][2];
    #pragma unroll
    for (int q = 0; q < 4; ++q) {
        const float* wr = &w_hh[(size_t)(q * 64 + wid * 8 + grp) * 64];
        #pragma unroll
        for (int kt = 0; kt < 4; ++kt) {
            int k = kt * 16 + 2 * tig;
            bf[q][kt][0] = f2h2u(wr[k],     wr[k + 1]);
            bf[q][kt][1] = f2h2u(wr[k + 8], wr[k + 9]);
        }
    }

    const int rp[4] = { grp * HW + tig,        (grp + 8) * HW + tig,
                        (grp + 16) * HW + tig, (grp + 24) * HW + tig };
    const int sp[4] = { grp * HW + wid * 4 + tig,        (grp + 8) * HW + wid * 4 + tig,
                        (grp + 16) * HW + wid * 4 + tig, (grp + 24) * HW + wid * 4 + tig };

    const __half2 half05 = __float2half2_rn(0.5f);
    __half2 creg[4];
    #pragma unroll
    for (int r = 0; r < 4; ++r) creg[r] = __float2half2_rn(0.f);

    __syncthreads();

    for (int t = 0; t < Tt; ++t) {
        const unsigned* rb   = &hsh[(t & 1) * HS];
        unsigned*       wbuf = &hsh[((t + 1) & 1) * HS];

        unsigned xl[4], xh[4];
        #pragma unroll
        for (int m = 0; m < 4; ++m) {
            int n = grp + 8 * m;
            xl[m] = xsh[t * (NB * 2) + n * 2];
            xh[m] = xsh[t * (NB * 2) + n * 2 + 1];
        }
        unsigned c[4][4];
        #pragma unroll
        for (int q = 0; q < 4; ++q) {
            #pragma unroll
            for (int m = 0; m < 4; ++m)
                c[q][m] = h2u(__hfma2(u2h(wb2[q]), u2h(xh[m]),
                              __hfma2(u2h(wa2[q]), u2h(xl[m]), u2h(bias2[q]))));
        }
        #pragma unroll
        for (int kt = 0; kt < 4; ++kt) {
            unsigned a0 = rb[rp[0] + kt * 8];
            unsigned a1 = rb[rp[1] + kt * 8];
            unsigned a2 = rb[rp[0] + kt * 8 + 4];
            unsigned a3 = rb[rp[1] + kt * 8 + 4];
            unsigned a4 = rb[rp[2] + kt * 8];
            unsigned a5 = rb[rp[3] + kt * 8];
            unsigned a6 = rb[rp[2] + kt * 8 + 4];
            unsigned a7 = rb[rp[3] + kt * 8 + 4];
            #pragma unroll
            for (int q = 0; q < 4; ++q) {
                mma_f16acc(c[q][0], c[q][1], a0, a1, a2, a3,
                           bf[q][kt][0], bf[q][kt][1]);
                mma_f16acc(c[q][2], c[q][3], a4, a5, a6, a7,
                           bf[q][kt][0], bf[q][kt][1]);
            }
        }

        #pragma unroll
        for (int r = 0; r < 4; ++r) {
            __half2 i2 = sig2(c[0][r], half05);
            __half2 f2 = sig2(c[1][r], half05);
            __half2 g2 = u2h(tanh2(c[2][r]));
            __half2 o2 = sig2(c[3][r], half05);
            creg[r] = __hfma2(f2, creg[r], __hmul2(i2, g2));
            wbuf[sp[r]] = h2u(__hmul2(o2, u2h(tanh2(h2u(creg[r])))));
        }
        __syncthreads();
    }

    // ============ fused GAT transform epilogue =====================
    // Final h is in buffer (Tt & 1) = 0, in A-fragment layout.
    const unsigned* hb = &hsh[0];

    // B fragments for gat_w: warp owns cols hg in [16w, 16w+16) as
    // two n-tiles (base 16w and 16w+8). gat_w row-major [hg][64].
    unsigned bg[2][4][2];
    #pragma unroll
    for (int nt = 0; nt < 2; ++nt) {
        const float* wr = &gat_w[(size_t)(wid * 16 + nt * 8 + grp) * 64];
        #pragma unroll
        for (int kt = 0; kt < 4; ++kt) {
            int k = kt * 16 + 2 * tig;
            bg[nt][kt][0] = f2h2u(wr[k],     wr[k + 1]);
            bg[nt][kt][1] = f2h2u(wr[k + 8], wr[k + 9]);
        }
    }

    float cx[2][2][4];   // [nt][mt][c0..c3]
    #pragma unroll
    for (int nt = 0; nt < 2; ++nt)
        #pragma unroll
        for (int mt = 0; mt < 2; ++mt)
            #pragma unroll
            for (int e = 0; e < 4; ++e) cx[nt][mt][e] = 0.f;

    #pragma unroll
    for (int kt = 0; kt < 4; ++kt) {
        unsigned a0 = hb[rp[0] + kt * 8];
        unsigned a1 = hb[rp[1] + kt * 8];
        unsigned a2 = hb[rp[0] + kt * 8 + 4];
        unsigned a3 = hb[rp[1] + kt * 8 + 4];
        unsigned a4 = hb[rp[2] + kt * 8];
        unsigned a5 = hb[rp[3] + kt * 8];
        unsigned a6 = hb[rp[2] + kt * 8 + 4];
        unsigned a7 = hb[rp[3] + kt * 8 + 4];
        #pragma unroll
        for (int nt = 0; nt < 2; ++nt) {
            mma_f32acc(cx[nt][0][0], cx[nt][0][1], cx[nt][0][2], cx[nt][0][3],
                       a0, a1, a2, a3, bg[nt][kt][0], bg[nt][kt][1]);
            mma_f32acc(cx[nt][1][0], cx[nt][1][1], cx[nt][1][2], cx[nt][1][3],
                       a4, a5, a6, a7, bg[nt][kt][0], bg[nt][kt][1]);
        }
    }

    // store xh + attention partials
    const int hg0  = wid * 16 + 2 * tig;       // nt0 col pair base
    const int hg1  = hg0 + 8;                  // nt1
    const int head = wid >> 2;
    const int p0   = head * 32 + ((hg0 & 63) >> 1);
    const int p1   = head * 32 + ((hg1 & 63) >> 1);
    const float2 as0 = make_float2(att_src[hg0], att_src[hg0 + 1]);
    const float2 as1 = make_float2(att_src[hg1], att_src[hg1 + 1]);
    const float2 ad0 = make_float2(att_dst[hg0], att_dst[hg0 + 1]);
    const float2 ad1 = make_float2(att_dst[hg1], att_dst[hg1 + 1]);
    const __half2 hz = __float2half2_rn(0.f);

    #pragma unroll
    for (int mt = 0; mt < 2; ++mt) {
        #pragma unroll
        for (int r = 0; r < 2; ++r) {
            int node = mt * 16 + grp + 8 * r;
            size_t n = base + node;
            float v00 = cx[0][mt][2 * r], v01 = cx[0][mt][2 * r + 1];
            float v10 = cx[1][mt][2 * r], v11 = cx[1][mt][2 * r + 1];
            g_xh2[n * 64 + p0]  = __floats2half2_rn(v00, v01);
            g_xh2[n * 64 + p1]  = __floats2half2_rn(v10, v11);
            g_acc2[n * 64 + p0] = hz;
            g_acc2[n * 64 + p1] = hz;
            float ps = v00 * as0.x + v01 * as0.y + v10 * as1.x + v11 * as1.y;
            float pd = v00 * ad0.x + v01 * ad0.y + v10 * ad1.x + v11 * ad1.y;
            ps += __shfl_xor_sync(0xffffffffu, ps, 1);
            ps += __shfl_xor_sync(0xffffffffu, ps, 2);
            pd += __shfl_xor_sync(0xffffffffu, pd, 1);
            pd += __shfl_xor_sync(0xffffffffu, pd, 2);
            if (tig == 0) {
                atomicAdd(&sm_as[head][node], ps);
                atomicAdd(&sm_ad[head][node], pd);
            }
        }
    }
    __syncthreads();
    if (tid < 64) {
        int node = tid & 31, hd = tid >> 5;
        size_t n = base + node;
        g_asrc[n * 2 + hd] = sm_as[hd][node];
        g_adst[n * 2 + hd] = sm_ad[hd][node];
        g_z[n * 2 + hd]    = 0.f;
    }
}

// ==================== GAT: exp-sum + weighted messages =============
// 8 lanes/edge; each lane owns one 16B chunk per head (2 independent
// v4.f16x2 reduction chains) -> better ILP at same atomic count.
__global__ void __launch_bounds__(256)
edge_sum_kernel(const int* __restrict__ ei32)
{
    int e   = (blockIdx.x * 256 + threadIdx.x) >> 3;
    int sub = threadIdx.x & 7;
    if (e >= ETOT) return;
    const int st = g_estride, of = g_eoff;
    int s, d;
    if (e < Ee) { s = ei32[(size_t)e * st]; d = ei32[(size_t)of + (size_t)e * st]; }
    else        { s = d = e - Ee; }

    float e0 = g_asrc[s * 2]     + g_adst[d * 2];
    float e1 = g_asrc[s * 2 + 1] + g_adst[d * 2 + 1];
    e0 = e0 > 0.f ? e0 : 0.2f * e0;
    e1 = e1 > 0.f ? e1 : 0.2f * e1;
    float w0 = __expf(e0);
    float w1 = __expf(e1);
    if (sub == 0) atomicAdd(&g_z[d * 2],     w0);
    if (sub == 1) atomicAdd(&g_z[d * 2 + 1], w1);

    __half2 c0 = __float2half2_rn(w0);
    __half2 c1 = __float2half2_rn(w1);
    const uint4* xb = (const uint4*)(g_xh2 + (size_t)s * 64);
    uint4 xv0 = xb[sub];
    uint4 xv1 = xb[8 + sub];
    unsigned m00 = h2u(__hmul2(u2h(xv0.x), c0));
    unsigned m01 = h2u(__hmul2(u2h(xv0.y), c0));
    unsigned m02 = h2u(__hmul2(u2h(xv0.z), c0));
    unsigned m03 = h2u(__hmul2(u2h(xv0.w), c0));
    unsigned m10 = h2u(__hmul2(u2h(xv1.x), c1));
    unsigned m11 = h2u(__hmul2(u2h(xv1.y), c1));
    unsigned m12 = h2u(__hmul2(u2h(xv1.z), c1));
    unsigned m13 = h2u(__hmul2(u2h(xv1.w), c1));
    __half2* ap0 = g_acc2 + (size_t)d * 64 + sub * 4;
    __half2* ap1 = ap0 + 32;
    asm volatile("red.global.add.noftz.v4.f16x2 [%0], {%1,%2,%3,%4};"
                 :: "l"(ap0), "r"(m00), "r"(m01), "r"(m02), "r"(m03) : "memory");
    asm volatile("red.global.add.noftz.v4.f16x2 [%0], {%1,%2,%3,%4};"
                 :: "l"(ap1), "r"(m10), "r"(m11), "r"(m12), "r"(m13) : "memory");
}

// ==================== finalize: mean heads + relu + linear + sigmoid
__global__ void __launch_bounds__(256)
final_kernel(const float* __restrict__ gat_b, const float* __restrict__ lin_w,
             const float* __restrict__ lin_b, float* __restrict__ out)
{
    int n    = (blockIdx.x * 256 + threadIdx.x) >> 5;
    int lane = threadIdx.x & 31;
    if (n >= Nn) return;
    float r0 = 0.5f / g_z[n * 2];
    float r1 = 0.5f / g_z[n * 2 + 1];
    float2 a0 = __half22float2(g_acc2[(size_t)n * 64 + lane]);
    float2 a1 = __half22float2(g_acc2[(size_t)n * 64 + 32 + lane]);
    float2 gb = ((const float2*)gat_b)[lane];
    float v0 = a0.x * r0 + a1.x * r1 + gb.x;
    float v1 = a0.y * r0 + a1.y * r1 + gb.y;
    v0 = v0 > 0.f ? v0 : 0.f;
    v1 = v1 > 0.f ? v1 : 0.f;
    float2 l0 = ((const float2*)lin_w)[lane];
    float2 l1 = ((const float2*)lin_w)[32 + lane];
    float y0 = v0 * l0.x + v1 * l0.y;
    float y1 = v0 * l1.x + v1 * l1.y;
    #pragma unroll
    for (int off = 16; off; off >>= 1) {
        y0 += __shfl_down_sync(0xffffffffu, y0, off);
        y1 += __shfl_down_sync(0xffffffffu, y1, off);
    }
    if (lane == 0) {
        out[n * 2]     = 1.f / (1.f + __expf(-(y0 + lin_b[0])));
        out[n * 2 + 1] = 1.f / (1.f + __expf(-(y1 + lin_b[1])));
    }
}

// ==================== launch =======================================
extern "C" void kernel_launch(void* const* d_in, const int* in_sizes, int n_in,
                              void* d_out, int out_size)
{
    const float* x       = (const float*)d_in[0];
    const int*   ei32    = (const int*)d_in[1];     // int32 view; probe decides layout
    const float* w_ih    = (const float*)d_in[2];
    const float* w_hh    = (const float*)d_in[3];
    const float* b_ih    = (const float*)d_in[4];
    const float* b_hh    = (const float*)d_in[5];
    const float* gat_w   = (const float*)d_in[6];
    const float* att_src = (const float*)d_in[7];
    const float* att_dst = (const float*)d_in[8];
    const float* gat_b   = (const float*)d_in[9];
    const float* lin_w   = (const float*)d_in[10];
    const float* lin_b   = (const float*)d_in[11];
    float*       out     = (float*)d_out;

    detect_kernel<<<1, 32>>>(ei32);
    lstm_kernel<<<Nn / NB, 256>>>(x, w_ih, w_hh, b_ih, b_hh,
                                  gat_w, att_src, att_dst);
    edge_sum_kernel<<<(ETOT * 8 + 255) / 256, 256>>>(ei32);
    final_kernel<<<Nn / 8, 256>>>(gat_b, lin_w, lin_b, out);
}